// round 5
// baseline (speedup 1.0000x reference)
#include <cuda_runtime.h>

#define NTPTS 144
#define L2E 1.4426950408889634f
#define TRC 0.0147f
#define T0C 1.8f
typedef unsigned long long u64;

static __device__ __forceinline__ float mlg2(float x){ float r; asm("lg2.approx.f32 %0, %1;":"=f"(r):"f"(x)); return r; }
static __device__ __forceinline__ float mex2(float x){ float r; asm("ex2.approx.f32 %0, %1;":"=f"(r):"f"(x)); return r; }
static __device__ __forceinline__ u64 pk2(float lo, float hi){ u64 r; asm("mov.b64 %0, {%1,%2};":"=l"(r):"f"(lo),"f"(hi)); return r; }
static __device__ __forceinline__ void upk2(float& lo, float& hi, u64 v){ asm("mov.b64 {%0,%1}, %2;":"=f"(lo),"=f"(hi):"l"(v)); }
static __device__ __forceinline__ u64 ffma2(u64 a, u64 b, u64 c){ u64 d; asm("fma.rn.f32x2 %0, %1, %2, %3;":"=l"(d):"l"(a),"l"(b),"l"(c)); return d; }
static __device__ __forceinline__ u64 fadd2(u64 a, u64 b){ u64 d; asm("add.rn.f32x2 %0, %1, %2;":"=l"(d):"l"(a),"l"(b)); return d; }

// Packed {x1,x2} incomplete-gamma difference:
//   G = P(a,x1) - P(a,x2),  P = exp2(a*lg2 x - L2E*x + c0) * Horner(rho, x)
// rho shared by both halves; K and 1/Gamma(a+1) folded into c0.
// x2<=0 half is garbage-but-finite in the Horner and predicated out.
template <int N>
static __device__ __forceinline__ float evalG(u64 xp, const u64* __restrict__ rp,
                                              float a, float c0)
{
    u64 S = rp[N];
#pragma unroll
    for (int n = N - 1; n >= 0; n--) S = ffma2(S, xp, rp[n]);
    float x1, x2; upk2(x1, x2, xp);
    float S1, S2; upk2(S1, S2, S);
    float y1 = fmaf(a, mlg2(x1), fmaf(-L2E, x1, c0));
    float P  = mex2(y1) * S1;
    if (x2 > 0.0f) {
        float y2 = fmaf(a, mlg2(x2), fmaf(-L2E, x2, c0));
        P -= mex2(y2) * S2;
    }
    return P;
}

// One warp per row. Lane owns j = 4*lane..4*lane+3 (vectorized LDS/STG.128),
// lanes 0..15 additionally own tail j = 128+lane. x generated analytically:
// x1(j) = x10 + j*step (t-grid is affine), no t-table loads.
template <int N>
static __device__ __forceinline__ void row_loop(int lane, float a, float c0,
                                                float x10, float step, float W,
                                                const float* __restrict__ sh_re,
                                                float* __restrict__ outp)
{
    u64 rp[N + 1];
    rp[0] = pk2(1.0f, 1.0f);
    float r = 1.0f, an = a;
#pragma unroll
    for (int n = 1; n <= N; n++) { an += 1.0f; r = __fdividef(r, an); rp[n] = pk2(r, r); }

    float bx1 = fmaf((float)(4 * lane), step, x10);
    u64 xp  = pk2(bx1, bx1 - W);
    u64 st2 = pk2(step, step);

    float4 res;
    res.x = evalG<N>(xp, rp, a, c0); xp = fadd2(xp, st2);
    res.y = evalG<N>(xp, rp, a, c0); xp = fadd2(xp, st2);
    res.z = evalG<N>(xp, rp, a, c0); xp = fadd2(xp, st2);
    res.w = evalG<N>(xp, rp, a, c0);

    float4 re4 = ((const float4*)sh_re)[lane];
    res.x *= re4.x; res.y *= re4.y; res.z *= re4.z; res.w *= re4.w;
    ((float4*)outp)[lane] = res;

    if (lane < 16) {
        float tx1 = fmaf((float)(128 + lane), step, x10);
        u64 txp = pk2(tx1, tx1 - W);
        outp[128 + lane] = sh_re[128 + lane] * evalG<N>(txp, rp, a, c0);
    }
}

__global__ void __launch_bounds__(256)
dynangio_kernel(const float4* __restrict__ xv4,
                const float* __restrict__ abuf,
                const float* __restrict__ rbuf,
                float* __restrict__ out, int nrows)
{
    __shared__ __align__(16) float sh_re[NTPTS];
    int tid = threadIdx.x;
    if (tid < NTPTS)
        sh_re[tid] = rbuf[tid] * sinf(abuf[tid] * 0.017453292519943295f);
    __syncthreads();

    int row = blockIdx.x * 8 + (tid >> 5);
    if (row >= nrows) return;
    int lane = tid & 31;

    float4 xv = xv4[row];
    float dt  = xv.x;
    float s   = xv.y;
    float pp  = xv.z;
    float amp = xv.w;

    const float INV_T1B = 0.60606060606060606f;    // 1/1.65

    float a      = fmaf(pp, s, 1.0f);              // a in [1,2)
    float sprime = s + INV_T1B;
    float step   = sprime * TRC;                   // s' * TR
    float W      = sprime * 1.8f;                  // s' * TAU
    float x10    = sprime * (T0C - dt);            // x1 at j=0
    // c0 = lg2( amp * 2 * exp(-dt/T1B) * (s/s')^a / Gamma(a+1) )
    float c0 = 1.0f
             - dt * INV_T1B * L2E
             + a * (mlg2(s) - mlg2(sprime))
             + mlg2(amp)
             - lgammaf(a + 1.0f) * L2E;

    // Warp-uniform series length from per-row max argument
    float x1max = fmaf(143.0f, step, x10);

    float* outp = out + (size_t)row * NTPTS;

    if (x1max <= 2.75f)
        row_loop<10>(lane, a, c0, x10, step, W, sh_re, outp);
    else if (x1max <= 4.5f)
        row_loop<14>(lane, a, c0, x10, step, W, sh_re, outp);
    else
        row_loop<19>(lane, a, c0, x10, step, W, sh_re, outp);
}

extern "C" void kernel_launch(void* const* d_in, const int* in_sizes, int n_in,
                              void* d_out, int out_size) {
    const float4* x  = (const float4*)d_in[0];   // (B,4) float32
    const float*  al = (const float*)d_in[2];    // (144,)
    const float*  R  = (const float*)d_in[3];    // (144,)
    float* out = (float*)d_out;                  // (B,144) float32
    int nrows  = in_sizes[0] / 4;
    int blocks = (nrows + 7) / 8;                // 8 warps/block, warp-per-row
    dynangio_kernel<<<blocks, 256>>>(x, al, R, out, nrows);
}

// round 7
// speedup vs baseline: 1.4440x; 1.4440x over previous
#include <cuda_runtime.h>

#define NTPTS 144
#define NSER  19
#define L2E 1.4426950408889634f
#define TRC 0.0147f
#define T0C 1.8f
typedef unsigned long long u64;

static __device__ __forceinline__ float mlg2(float x){ float r; asm("lg2.approx.f32 %0, %1;":"=f"(r):"f"(x)); return r; }
static __device__ __forceinline__ float mex2(float x){ float r; asm("ex2.approx.f32 %0, %1;":"=f"(r):"f"(x)); return r; }
static __device__ __forceinline__ u64 pk2(float lo, float hi){ u64 r; asm("mov.b64 %0, {%1,%2};":"=l"(r):"f"(lo),"f"(hi)); return r; }
static __device__ __forceinline__ void upk2(float& lo, float& hi, u64 v){ asm("mov.b64 {%0,%1}, %2;":"=f"(lo),"=f"(hi):"l"(v)); }
static __device__ __forceinline__ u64 ffma2(u64 a, u64 b, u64 c){ u64 d; asm("fma.rn.f32x2 %0, %1, %2, %3;":"=l"(d):"l"(a),"l"(b),"l"(c)); return d; }
static __device__ __forceinline__ u64 fadd2(u64 a, u64 b){ u64 d; asm("add.rn.f32x2 %0, %1, %2;":"=l"(d):"l"(a),"l"(b)); return d; }

// Packed {x1,x2} incomplete-gamma difference:
//   G = P(a,x1) - P(a,x2),  P = exp2(a*lg2 x - L2E*x + c0) * Horner(rho, x)
// rho shared by both halves (one packed Horner); amp*SF/Gamma(a+1) folded into c0.
// x2<=0: Horner half is garbage-but-finite, prefactor is NaN, selected to 0.
static __device__ __forceinline__ float evalG(u64 xp, const u64* __restrict__ rp,
                                              float a, float c0)
{
    u64 S = rp[NSER];
#pragma unroll
    for (int n = NSER - 1; n >= 0; n--) S = ffma2(S, xp, rp[n]);
    float x1, x2; upk2(x1, x2, xp);
    float S1, S2; upk2(S1, S2, S);
    float y1 = fmaf(a, mlg2(x1), fmaf(-L2E, x1, c0));
    float y2 = fmaf(a, mlg2(x2), fmaf(-L2E, x2, c0));
    float P1 = mex2(y1) * S1;
    float P2 = (x2 > 0.0f) ? mex2(y2) * S2 : 0.0f;   // select, branch-free
    return P1 - P2;
}

// Thread-per-row: row setup (rho, lgamma, prefactor) amortized over 144 outputs.
__global__ void __launch_bounds__(128)
dynangio_kernel(const float4* __restrict__ xv4,
                const float* __restrict__ abuf,
                const float* __restrict__ rbuf,
                float* __restrict__ out, int nrows)
{
    __shared__ __align__(16) float sh_re[NTPTS];
    int tid = threadIdx.x;
    for (int i = tid; i < NTPTS; i += 128)
        sh_re[i] = rbuf[i] * sinf(abuf[i] * 0.017453292519943295f);
    __syncthreads();

    int row = blockIdx.x * 128 + tid;
    if (row >= nrows) return;

    float4 xv = xv4[row];
    float dt  = xv.x;
    float s   = xv.y;
    float pp  = xv.z;
    float amp = xv.w;

    const float INV_T1B = 0.60606060606060606f;    // 1/1.65

    float a      = fmaf(pp, s, 1.0f);              // a in [1,2)
    float sprime = s + INV_T1B;
    float step   = sprime * TRC;                   // s' * TR
    float W      = sprime * 1.8f;                  // s' * TAU
    float x10    = sprime * (T0C - dt);            // x1 at j=0 (>= 0.48)
    // c0 = lg2( amp * 2 * exp(-dt/T1B) * (s/s')^a / Gamma(a+1) )
    float c0 = 1.0f
             - dt * INV_T1B * L2E
             + a * (mlg2(s) - mlg2(sprime))
             + mlg2(amp)
             - lgammaf(a + 1.0f) * L2E;

    // rho[n] = 1/prod_{k=1..n}(a+k), duplicated into packed pairs (registers)
    u64 rp[NSER + 1];
    rp[0] = pk2(1.0f, 1.0f);
    float r = 1.0f, an = a;
#pragma unroll
    for (int n = 1; n <= NSER; n++) { an += 1.0f; r = __fdividef(r, an); rp[n] = pk2(r, r); }

    u64 st2 = pk2(step, step);
    float* outp = out + (size_t)row * NTPTS;
    const float4* re4 = (const float4*)sh_re;

#pragma unroll 4
    for (int ji = 0; ji < NTPTS / 4; ji++) {
        int j = ji * 4;
        // fresh base per chunk: no rounding accumulation over the row
        float xb = fmaf((float)j, step, x10);
        u64 xp = pk2(xb, xb - W);

        float4 res;
        res.x = evalG(xp, rp, a, c0); xp = fadd2(xp, st2);
        res.y = evalG(xp, rp, a, c0); xp = fadd2(xp, st2);
        res.z = evalG(xp, rp, a, c0); xp = fadd2(xp, st2);
        res.w = evalG(xp, rp, a, c0);

        float4 re = re4[ji];                        // LDS.128, warp-broadcast
        res.x *= re.x; res.y *= re.y; res.z *= re.z; res.w *= re.w;
        ((float4*)outp)[ji] = res;
    }
}

extern "C" void kernel_launch(void* const* d_in, const int* in_sizes, int n_in,
                              void* d_out, int out_size) {
    const float4* x  = (const float4*)d_in[0];   // (B,4) float32
    const float*  al = (const float*)d_in[2];    // (144,)
    const float*  R  = (const float*)d_in[3];    // (144,)
    float* out = (float*)d_out;                  // (B,144) float32
    int nrows  = in_sizes[0] / 4;
    int blocks = (nrows + 127) / 128;            // thread-per-row
    dynangio_kernel<<<blocks, 128>>>(x, al, R, out, nrows);
}